// round 2
// baseline (speedup 1.0000x reference)
#include <cuda_runtime.h>
#include <cstdint>
#include <cstdio>

// Problem constants
#define ALPHA_C 0.2f
#define NSTD_C  0.05f

constexpr int B = 64, T = 1024, H = 512, IN = 64, OUT = 8;
constexpr int KTOT = H + IN;          // 576: [relu(h) ; x] concatenated K
constexpr int CLUSTER = 8;            // CTAs per cluster (portable max)
constexpr int BPC = 4;                // batches per cluster
constexpr int NCLUS = B / BPC;        // 16 clusters
constexpr int HC = H / CLUSTER;       // 64 output columns per CTA
constexpr int NTHREADS = 512;
constexpr int NSLICE = 8;             // k-slices per column
constexpr int KS = KTOT / NSLICE;     // 72 k per slice
constexpr int W_PITCH = 580;          // 576 + 4 pad (bank-conflict-free LDS.128)
constexpr int R_ROW = 576;

// Shared memory layout (floats)
constexpr int OFF_W   = 0;                         // [HC][W_PITCH]
constexpr int OFF_R0  = OFF_W  + HC * W_PITCH;     // [BPC][R_ROW]
constexpr int OFF_R1  = OFF_R0 + BPC * R_ROW;
constexpr int OFF_RED = OFF_R1 + BPC * R_ROW;      // [NSLICE][256]
constexpr int OFF_STG = OFF_RED + NSLICE * 256;    // [256]
constexpr int SMEM_FLOATS = OFF_STG + 256;
constexpr int SMEM_BYTES = SMEM_FLOATS * 4;        // 176128 B

// Scratch for effective transposed weight: wT[col][k], k in [0,576)
__device__ float g_wT[H * KTOT];

// ---------------------------------------------------------------------------
// Phase 0: build wT[col][k] = |wrec[k][col]|*wrec_mask  (k<512)
//                            wi[i][col]*si[i]*wi_mask   (k=512+i)
// ---------------------------------------------------------------------------
__global__ void prep_kernel(const float* __restrict__ wrec,
                            const float* __restrict__ wrec_mask,
                            const float* __restrict__ wi,
                            const float* __restrict__ si,
                            const float* __restrict__ wi_mask)
{
    int idx = blockIdx.x * blockDim.x + threadIdx.x;
    if (idx >= KTOT * H) return;
    int k   = idx >> 9;        // 0..575
    int col = idx & (H - 1);   // 0..511
    float v;
    if (k < H) {
        v = fabsf(wrec[k * H + col]) * wrec_mask[k * H + col];
    } else {
        int i = k - H;
        v = wi[i * H + col] * si[i] * wi_mask[i * H + col];
    }
    g_wT[col * KTOT + k] = v;
}

// ---------------------------------------------------------------------------
// Phase 1: the recurrence. Persistent cluster kernel.
// ---------------------------------------------------------------------------
__device__ __forceinline__ void fma2(unsigned long long& d,
                                     unsigned long long a,
                                     unsigned long long b)
{
    asm("fma.rn.f32x2 %0, %1, %2, %0;" : "+l"(d) : "l"(a), "l"(b));
}

extern "C" __global__ void __launch_bounds__(NTHREADS, 1)
rnn_kernel(const float* __restrict__ input,   // [B][T][IN]
           const float* __restrict__ noise,   // [B][T][H]
           const float* __restrict__ bias,    // [H]
           const float* __restrict__ h0,      // [H]
           float* __restrict__ traj)          // [B][T+1][H]
{
    extern __shared__ float smem[];
    float* w_s   = smem + OFF_W;
    float* r0    = smem + OFF_R0;
    float* r1    = smem + OFF_R1;
    float* red   = smem + OFF_RED;
    float* stage = smem + OFF_STG;

    const int tid    = threadIdx.x;
    const int rank   = blockIdx.x & (CLUSTER - 1);
    const int cid    = blockIdx.x / CLUSTER;
    const int batch0 = cid * BPC;
    const int col0   = rank * HC;

    // Load this CTA's 64 columns of wT into SMEM
    for (int idx = tid; idx < HC * KTOT; idx += NTHREADS) {
        int j = idx / KTOT, k = idx - j * KTOT;
        w_s[j * W_PITCH + k] = g_wT[(col0 + j) * KTOT + k];
    }
    // Init r0 = [relu(h0) ; x_0] for the cluster's 4 batches
    for (int idx = tid; idx < BPC * H; idx += NTHREADS) {
        int bb = idx >> 9, k = idx & (H - 1);
        r0[bb * R_ROW + k] = fmaxf(h0[k], 0.f);
    }
    if (tid < BPC * IN) {
        int bb = tid >> 6, i = tid & (IN - 1);
        r0[bb * R_ROW + H + i] = input[(size_t)(batch0 + bb) * T * IN + i];
    }

    // Update-role mapping (threads 0..255): (bb_u, j_u)
    const int bb_u = tid >> 6;
    const int j_u  = tid & 63;
    const int jg   = col0 + j_u;
    float h_reg = 0.f, bias_reg = 0.f;
    if (tid < 256) {
        h_reg    = h0[jg];
        bias_reg = bias[jg];
        traj[(size_t)(batch0 + bb_u) * (T + 1) * H + jg] = h_reg;  // t=0 row
    }
    __syncthreads();

    // GEMM-role mapping: jj = column within chunk, s = k-slice
    const int jj = tid & 63;
    const int s  = tid >> 6;
    const float* wrow = w_s + jj * W_PITCH + s * KS;
    const uint32_t r0_sh = (uint32_t)__cvta_generic_to_shared(r0);
    const uint32_t r1_sh = (uint32_t)__cvta_generic_to_shared(r1);

    for (int t = 0; t < T; t++) {
        float* rcur = (t & 1) ? r1 : r0;
        float* rnxt = (t & 1) ? r0 : r1;

        // Issue global loads early (hidden behind GEMM)
        float nval = 0.f, xval = 0.f;
        if (tid < 256) {
            nval = noise[(size_t)(batch0 + bb_u) * T * H + (size_t)t * H + jg];
            if (t + 1 < T)
                xval = input[(size_t)(batch0 + bb_u) * T * IN + (size_t)(t + 1) * IN + j_u];
        }

        // Partial GEMM: acc[b] = sum over this thread's k-slice of r[b][k]*w[k][jj]
        unsigned long long aA0 = 0, aA1 = 0, aA2 = 0, aA3 = 0;
        unsigned long long aB0 = 0, aB1 = 0, aB2 = 0, aB3 = 0;
        const float* rbase = rcur + s * KS;
        #pragma unroll
        for (int kk = 0; kk < KS; kk += 4) {
            ulonglong2 w = *(const ulonglong2*)(wrow + kk);
            ulonglong2 ra = *(const ulonglong2*)(rbase + 0 * R_ROW + kk);
            fma2(aA0, ra.x, w.x); fma2(aB0, ra.y, w.y);
            ulonglong2 rb = *(const ulonglong2*)(rbase + 1 * R_ROW + kk);
            fma2(aA1, rb.x, w.x); fma2(aB1, rb.y, w.y);
            ulonglong2 rc = *(const ulonglong2*)(rbase + 2 * R_ROW + kk);
            fma2(aA2, rc.x, w.x); fma2(aB2, rc.y, w.y);
            ulonglong2 rd = *(const ulonglong2*)(rbase + 3 * R_ROW + kk);
            fma2(aA3, rd.x, w.x); fma2(aB3, rd.y, w.y);
        }
        {
            float2 a, b2;
            a = *(float2*)&aA0; b2 = *(float2*)&aB0;
            red[s * 256 + 0 * 64 + jj] = a.x + a.y + b2.x + b2.y;
            a = *(float2*)&aA1; b2 = *(float2*)&aB1;
            red[s * 256 + 1 * 64 + jj] = a.x + a.y + b2.x + b2.y;
            a = *(float2*)&aA2; b2 = *(float2*)&aB2;
            red[s * 256 + 2 * 64 + jj] = a.x + a.y + b2.x + b2.y;
            a = *(float2*)&aA3; b2 = *(float2*)&aB3;
            red[s * 256 + 3 * 64 + jj] = a.x + a.y + b2.x + b2.y;
        }
        __syncthreads();

        // Reduce slices, elementwise update, store trajectory, stage relu
        if (tid < 256) {
            float tot = 0.f;
            #pragma unroll
            for (int ss = 0; ss < NSLICE; ss++) tot += red[ss * 256 + tid];
            float hnew = h_reg + NSTD_C * nval + ALPHA_C * (-h_reg + tot + bias_reg);
            traj[(size_t)(batch0 + bb_u) * (T + 1) * H + (size_t)(t + 1) * H + jg] = hnew;
            h_reg = hnew;
            stage[tid] = fmaxf(hnew, 0.f);
            rnxt[bb_u * R_ROW + H + j_u] = xval;  // x_{t+1} into next r buffer (local)
        }
        __syncthreads();

        // DSMEM multicast: broadcast this CTA's relu chunk [4][64] to all 8 CTAs
        {
            const uint32_t rnxt_sh = (t & 1) ? r0_sh : r1_sh;
            int p  = tid & 127;            // 128 x u64 pairs cover 256 floats
            int g  = tid >> 7;             // 0..3 -> ranks {g, g+4}
            int bb = p >> 5;
            int j0 = (p & 31) * 2;
            unsigned long long v = *(const unsigned long long*)(stage + p * 2);
            uint32_t laddr = rnxt_sh + (uint32_t)((bb * R_ROW + col0 + j0) * 4);
            uint32_t remote;
            asm volatile("mapa.shared::cluster.u32 %0, %1, %2;"
                         : "=r"(remote) : "r"(laddr), "r"(g));
            asm volatile("st.shared::cluster.u64 [%0], %1;"
                         :: "r"(remote), "l"(v) : "memory");
            asm volatile("mapa.shared::cluster.u32 %0, %1, %2;"
                         : "=r"(remote) : "r"(laddr), "r"(g + 4));
            asm volatile("st.shared::cluster.u64 [%0], %1;"
                         :: "r"(remote), "l"(v) : "memory");
        }

        // One cluster barrier per step (release/acquire orders DSMEM stores)
        asm volatile("barrier.cluster.arrive.aligned;" ::: "memory");
        asm volatile("barrier.cluster.wait.aligned;" ::: "memory");
    }
}

// ---------------------------------------------------------------------------
// Phase 2: output = relu(traj[:,1:,:]) @ wo_eff.  One warp per (b,t).
// ---------------------------------------------------------------------------
__global__ void out_kernel(const float* __restrict__ traj,
                           const float* __restrict__ wo,
                           const float* __restrict__ so,
                           const float* __restrict__ wo_mask,
                           float* __restrict__ out)
{
    __shared__ float swo[H * OUT];  // 16 KB
    int tid = threadIdx.x;
    for (int idx = tid; idx < H * OUT; idx += 256) {
        int o = idx & (OUT - 1);
        swo[idx] = wo[idx] * so[o] * wo_mask[idx];
    }
    __syncthreads();

    int warp = blockIdx.x * 8 + (tid >> 5);
    int lane = tid & 31;
    int b = warp >> 10, t = warp & 1023;
    const float* row = traj + (size_t)b * (T + 1) * H + (size_t)(t + 1) * H;

    float acc[OUT];
    #pragma unroll
    for (int o = 0; o < OUT; o++) acc[o] = 0.f;

    #pragma unroll
    for (int u = 0; u < H / 32; u++) {
        int k = lane + u * 32;
        float v = fmaxf(row[k], 0.f);
        float4 w0 = *(const float4*)&swo[k * OUT];
        float4 w1 = *(const float4*)&swo[k * OUT + 4];
        acc[0] += v * w0.x; acc[1] += v * w0.y; acc[2] += v * w0.z; acc[3] += v * w0.w;
        acc[4] += v * w1.x; acc[5] += v * w1.y; acc[6] += v * w1.z; acc[7] += v * w1.w;
    }
    #pragma unroll
    for (int o = 0; o < OUT; o++) {
        #pragma unroll
        for (int off = 16; off; off >>= 1)
            acc[o] += __shfl_down_sync(0xffffffffu, acc[o], off);
    }
    if (lane == 0) {
        float4* op = (float4*)(out + (size_t)warp * OUT);
        op[0] = make_float4(acc[0], acc[1], acc[2], acc[3]);
        op[1] = make_float4(acc[4], acc[5], acc[6], acc[7]);
    }
}

// ---------------------------------------------------------------------------
// kernel_launch
// ---------------------------------------------------------------------------
extern "C" void kernel_launch(void* const* d_in, const int* in_sizes, int n_in,
                              void* d_out, int out_size)
{
    (void)in_sizes; (void)n_in; (void)out_size;
    const float* input     = (const float*)d_in[0];
    const float* noise     = (const float*)d_in[1];
    const float* wi        = (const float*)d_in[2];
    const float* si        = (const float*)d_in[3];
    const float* wrec      = (const float*)d_in[4];
    const float* bias      = (const float*)d_in[5];
    const float* wo        = (const float*)d_in[6];
    const float* so        = (const float*)d_in[7];
    const float* wi_mask   = (const float*)d_in[8];
    const float* wrec_mask = (const float*)d_in[9];
    const float* wo_mask   = (const float*)d_in[10];
    const float* h0        = (const float*)d_in[11];

    float* out  = (float*)d_out;
    float* traj = out + (size_t)B * T * OUT;   // output first, trajectories after

    // Phase 0: effective transposed weights
    prep_kernel<<<(KTOT * H + 255) / 256, 256>>>(wrec, wrec_mask, wi, si, wi_mask);

    // Phase 1: clustered recurrence
    cudaFuncSetAttribute(rnn_kernel, cudaFuncAttributeMaxDynamicSharedMemorySize,
                         SMEM_BYTES);
    cudaLaunchConfig_t cfg = {};
    cfg.gridDim  = dim3(NCLUS * CLUSTER, 1, 1);
    cfg.blockDim = dim3(NTHREADS, 1, 1);
    cfg.dynamicSmemBytes = SMEM_BYTES;
    cfg.stream = 0;
    cudaLaunchAttribute attrs[1];
    attrs[0].id = cudaLaunchAttributeClusterDimension;
    attrs[0].val.clusterDim.x = CLUSTER;
    attrs[0].val.clusterDim.y = 1;
    attrs[0].val.clusterDim.z = 1;
    cfg.attrs = attrs;
    cfg.numAttrs = 1;
    cudaLaunchKernelEx(&cfg, rnn_kernel, input, noise, bias, h0, traj);

    // Phase 2: readout
    out_kernel<<<(B * T) / 8, 256>>>(traj, wo, so, wo_mask, out);
}

// round 4
// speedup vs baseline: 1.1300x; 1.1300x over previous
#include <cuda_runtime.h>
#include <cstdint>

#define ALPHA_C 0.2f
#define NSTD_C  0.05f

constexpr int B = 64, T = 1024, H = 512, IN = 64, OUT = 8;
constexpr int KTOT = H + IN;         // 576
constexpr int CLUSTER = 8;
constexpr int BPC = 4;               // batches per cluster
constexpr int NCLUS = B / BPC;       // 16
constexpr int HC = H / CLUSTER;      // 64 cols per CTA
constexpr int NT = 512;
constexpr int NSLICE = 8;
constexpr int KS = KTOT / NSLICE;    // 72

typedef unsigned long long ull;

__device__ __forceinline__ void fma2(ull& d, ull a, ull b) {
    asm("fma.rn.f32x2 %0, %1, %2, %0;" : "+l"(d) : "l"(a), "l"(b));
}
__device__ __forceinline__ uint32_t mapa_sh(uint32_t la, int peer) {
    uint32_t ra;
    asm volatile("mapa.shared::cluster.u32 %0, %1, %2;" : "=r"(ra) : "r"(la), "r"(peer));
    return ra;
}

__global__ void zero_out(float* out) {
    int i = blockIdx.x * blockDim.x + threadIdx.x;
    if (i < B * T * OUT) out[i] = 0.f;
}

struct __align__(16) SM {
    float r[2][BPC][KTOT];      // 18432 B  (double-buffered [relu(h); x])
    float red[NSLICE][256];     //  8192 B
    float stage[256];           //  1024 B
    float wo[HC][OUT];          //  2048 B
};

__device__ __forceinline__ float effw(int k, int col,
                                      const float* __restrict__ wrec,
                                      const float* __restrict__ wrec_mask,
                                      const float* __restrict__ wi,
                                      const float* __restrict__ si,
                                      const float* __restrict__ wi_mask)
{
    if (k < H) return fabsf(wrec[k * H + col]) * wrec_mask[k * H + col];
    int i = k - H;
    return wi[i * H + col] * si[i] * wi_mask[i * H + col];
}

__global__ void __launch_bounds__(NT, 1) __cluster_dims__(CLUSTER, 1, 1)
rnn_kernel(const float* __restrict__ input,     // [B][T][IN]
           const float* __restrict__ noise,     // [B][T][H]
           const float* __restrict__ wi,
           const float* __restrict__ si,
           const float* __restrict__ wrec,
           const float* __restrict__ bias,
           const float* __restrict__ wo,
           const float* __restrict__ so,
           const float* __restrict__ wi_mask,
           const float* __restrict__ wrec_mask,
           const float* __restrict__ wo_mask,
           const float* __restrict__ h0,
           float* __restrict__ traj,            // [B][T+1][H]
           float* __restrict__ out)             // [B][T][OUT]
{
    __shared__ SM sm;

    const int tid    = threadIdx.x;
    const int rank   = blockIdx.x & (CLUSTER - 1);
    const int batch0 = (blockIdx.x >> 3) * BPC;
    const int col0   = rank * HC;
    const int jj     = tid & 63;
    const int s      = tid >> 6;            // 0..7 k-slice
    const int col    = col0 + jj;

    // ---- this thread's 72 effective weights -> 36 packed f32x2 registers ----
    ull w[36];
    #pragma unroll
    for (int i = 0; i < 36; i++) {
        int k0 = s * KS + 2 * i;
        float v0 = effw(k0,     col, wrec, wrec_mask, wi, si, wi_mask);
        float v1 = effw(k0 + 1, col, wrec, wrec_mask, wi, si, wi_mask);
        w[i] = (ull)__float_as_uint(v0) | ((ull)__float_as_uint(v1) << 32);
    }

    // ---- shared init: r[0] = [relu(h0); x_0], wo_eff slice ----
    for (int idx = tid; idx < BPC * H; idx += NT) {
        int bb = idx >> 9, k = idx & (H - 1);
        sm.r[0][bb][k] = fmaxf(h0[k], 0.f);
    }
    if (tid < BPC * IN) {
        int bb = tid >> 6, ii = tid & (IN - 1);
        sm.r[0][bb][H + ii] = input[(size_t)(batch0 + bb) * T * IN + ii];
    }
    for (int idx = tid; idx < HC * OUT; idx += NT) {
        int j = idx >> 3, o = idx & (OUT - 1);
        sm.wo[j][o] = wo[(col0 + j) * OUT + o] * so[o] * wo_mask[(col0 + j) * OUT + o];
    }

    // ---- update-role state (threads 0..255 own (bb_u, j_u)) ----
    const int bb_u = tid >> 6;
    const int j_u  = tid & 63;
    const int jg   = col0 + j_u;
    float h_reg = 0.f, bias_reg = 0.f;
    const float* np = noise;
    const float* xp = input;
    float* tp = traj;
    float* op = out;
    if (tid < 256) {
        h_reg    = h0[jg];
        bias_reg = bias[jg];
        tp = traj + (size_t)(batch0 + bb_u) * (T + 1) * H + jg;
        *tp = h_reg;                // t = 0 trajectory row
        tp += H;
        np = noise + (size_t)(batch0 + bb_u) * T * H + jg;
        xp = input + (size_t)(batch0 + bb_u) * T * IN + j_u + IN;  // x_{t+1}
        op = out   + (size_t)(batch0 + bb_u) * T * OUT;
    }

    const uint32_t r0_sh = (uint32_t)__cvta_generic_to_shared(&sm.r[0][0][0]);
    const uint32_t r1_sh = (uint32_t)__cvta_generic_to_shared(&sm.r[1][0][0]);

    __syncthreads();
    asm volatile("barrier.cluster.arrive.aligned;" ::: "memory");
    asm volatile("barrier.cluster.wait.aligned;" ::: "memory");

    for (int t = 0; t < T; t++) {
        const int p = t & 1;

        // prefetch noise(t) / x(t+1): DRAM latency hides behind the GEMM
        float nval = 0.f, xval = 0.f;
        if (tid < 256) {
            nval = __ldg(np); np += H;
            if (t + 1 < T) { xval = __ldg(xp); xp += IN; }
        }

        // ---- GEMM: acc[b] = sum_k r[p][b][k] * w[k][col], this k-slice ----
        const float* rb = &sm.r[p][0][s * KS];
        ull a0 = 0, a1 = 0, a2 = 0, a3 = 0;
        #pragma unroll
        for (int kk = 0; kk < KS / 4; kk++) {
            ulonglong2 v0 = *(const ulonglong2*)(rb + 0 * KTOT + kk * 4);
            ulonglong2 v1 = *(const ulonglong2*)(rb + 1 * KTOT + kk * 4);
            ulonglong2 v2 = *(const ulonglong2*)(rb + 2 * KTOT + kk * 4);
            ulonglong2 v3 = *(const ulonglong2*)(rb + 3 * KTOT + kk * 4);
            fma2(a0, v0.x, w[2 * kk]);     fma2(a1, v1.x, w[2 * kk]);
            fma2(a2, v2.x, w[2 * kk]);     fma2(a3, v3.x, w[2 * kk]);
            fma2(a0, v0.y, w[2 * kk + 1]); fma2(a1, v1.y, w[2 * kk + 1]);
            fma2(a2, v2.y, w[2 * kk + 1]); fma2(a3, v3.y, w[2 * kk + 1]);
        }
        {
            float2 f;
            f = *(float2*)&a0; sm.red[s][  0 + jj] = f.x + f.y;
            f = *(float2*)&a1; sm.red[s][ 64 + jj] = f.x + f.y;
            f = *(float2*)&a2; sm.red[s][128 + jj] = f.x + f.y;
            f = *(float2*)&a3; sm.red[s][192 + jj] = f.x + f.y;
        }
        __syncthreads();

        // ---- reduce slices, state update, trajectory, stage relu, readout ----
        if (tid < 256) {
            float tot = sm.red[0][tid] + sm.red[1][tid] + sm.red[2][tid] + sm.red[3][tid]
                      + sm.red[4][tid] + sm.red[5][tid] + sm.red[6][tid] + sm.red[7][tid];
            float hnew = h_reg + NSTD_C * nval + ALPHA_C * (tot + bias_reg - h_reg);
            *tp = hnew; tp += H;
            h_reg = hnew;
            float v = fmaxf(hnew, 0.f);
            sm.stage[tid] = v;
            if (t + 1 < T)
                sm.r[p ^ 1][bb_u][H + j_u] = xval;   // local x_{t+1}

            // fused readout: 64 cols -> 8 outputs per batch, warp-reduced
            float4 w0 = *(const float4*)&sm.wo[j_u][0];
            float4 w1 = *(const float4*)&sm.wo[j_u][4];
            float p0 = v * w0.x, p1 = v * w0.y, p2 = v * w0.z, p3 = v * w0.w;
            float p4 = v * w1.x, p5 = v * w1.y, p6 = v * w1.z, p7 = v * w1.w;
            #pragma unroll
            for (int off = 16; off; off >>= 1) {
                p0 += __shfl_down_sync(0xffffffffu, p0, off);
                p1 += __shfl_down_sync(0xffffffffu, p1, off);
                p2 += __shfl_down_sync(0xffffffffu, p2, off);
                p3 += __shfl_down_sync(0xffffffffu, p3, off);
                p4 += __shfl_down_sync(0xffffffffu, p4, off);
                p5 += __shfl_down_sync(0xffffffffu, p5, off);
                p6 += __shfl_down_sync(0xffffffffu, p6, off);
                p7 += __shfl_down_sync(0xffffffffu, p7, off);
            }
            if ((tid & 31) == 0) {
                float* ob = op + (size_t)t * OUT;
                atomicAdd(ob + 0, p0); atomicAdd(ob + 1, p1);
                atomicAdd(ob + 2, p2); atomicAdd(ob + 3, p3);
                atomicAdd(ob + 4, p4); atomicAdd(ob + 5, p5);
                atomicAdd(ob + 6, p6); atomicAdd(ob + 7, p7);
            }
        }
        __syncthreads();

        // ---- DSMEM multicast of this CTA's relu chunk to all 8 CTAs ----
        if (t + 1 < T) {
            const uint32_t rnxt_sh = (p ? r0_sh : r1_sh);
            int pp = tid & 127;            // 128 u64 pairs cover 256 floats
            int g  = tid >> 7;             // 0..3 -> ranks {g, g+4}
            int bb = pp >> 5;
            int j0 = (pp & 31) * 2;
            ull v = *(const ull*)(sm.stage + pp * 2);
            uint32_t laddr = rnxt_sh + (uint32_t)((bb * KTOT + col0 + j0) * 4);
            uint32_t ra = mapa_sh(laddr, g);
            asm volatile("st.shared::cluster.u64 [%0], %1;" :: "r"(ra), "l"(v) : "memory");
            ra = mapa_sh(laddr, g + 4);
            asm volatile("st.shared::cluster.u64 [%0], %1;" :: "r"(ra), "l"(v) : "memory");
        }

        // one cluster barrier per step (orders DSMEM stores, releases next GEMM)
        asm volatile("barrier.cluster.arrive.aligned;" ::: "memory");
        asm volatile("barrier.cluster.wait.aligned;" ::: "memory");
    }
}

// ---------------------------------------------------------------------------
extern "C" void kernel_launch(void* const* d_in, const int* in_sizes, int n_in,
                              void* d_out, int out_size)
{
    (void)in_sizes; (void)n_in; (void)out_size;
    const float* input     = (const float*)d_in[0];
    const float* noise     = (const float*)d_in[1];
    const float* wi        = (const float*)d_in[2];
    const float* si        = (const float*)d_in[3];
    const float* wrec      = (const float*)d_in[4];
    const float* bias      = (const float*)d_in[5];
    const float* wo        = (const float*)d_in[6];
    const float* so        = (const float*)d_in[7];
    const float* wi_mask   = (const float*)d_in[8];
    const float* wrec_mask = (const float*)d_in[9];
    const float* wo_mask   = (const float*)d_in[10];
    const float* h0        = (const float*)d_in[11];

    float* out  = (float*)d_out;
    float* traj = out + (size_t)B * T * OUT;

    zero_out<<<(B * T * OUT + 255) / 256, 256>>>(out);

    rnn_kernel<<<NCLUS * CLUSTER, NT>>>(input, noise, wi, si, wrec, bias, wo, so,
                                        wi_mask, wrec_mask, wo_mask, h0, traj, out);
}

// round 5
// speedup vs baseline: 1.4684x; 1.2995x over previous
#include <cuda_runtime.h>
#include <cstdint>

#define ALPHA_C 0.2f
#define NSTD_C  0.05f

constexpr int B = 64, T = 1024, H = 512, IN = 64, OUT = 8;
constexpr int KTOT = H + IN;         // 576
constexpr int CLUSTER = 8;
constexpr int BPC = 4;               // batches per cluster
constexpr int NCLUS = B / BPC;       // 16
constexpr int HC = H / CLUSTER;      // 64 cols per CTA
constexpr int NT = 512;
constexpr int NSLICE = 16;
constexpr int KS = KTOT / NSLICE;    // 36
constexpr int TXB = CLUSTER * BPC * HC * 4;   // 8192 bytes per phase per barrier

typedef unsigned long long ull;

__device__ __forceinline__ void fma2(ull& d, ull a, ull b) {
    asm("fma.rn.f32x2 %0, %1, %2, %0;" : "+l"(d) : "l"(a), "l"(b));
}
__device__ __forceinline__ uint32_t mapa_sh(uint32_t la, int peer) {
    uint32_t ra;
    asm volatile("mapa.shared::cluster.u32 %0, %1, %2;" : "=r"(ra) : "r"(la), "r"(peer));
    return ra;
}
__device__ __forceinline__ void mbar_init(uint32_t mb, uint32_t cnt) {
    asm volatile("mbarrier.init.shared.b64 [%0], %1;" :: "r"(mb), "r"(cnt) : "memory");
}
__device__ __forceinline__ void mbar_expect(uint32_t mb, uint32_t bytes) {
    asm volatile("mbarrier.arrive.expect_tx.shared.b64 _, [%0], %1;"
                 :: "r"(mb), "r"(bytes) : "memory");
}
__device__ __forceinline__ void mbar_wait(uint32_t mb, uint32_t phase) {
    uint32_t done;
    asm volatile(
        "{\n\t.reg .pred p;\n\t"
        "mbarrier.try_wait.parity.acquire.cta.shared::cta.b64 p, [%1], %2;\n\t"
        "selp.b32 %0, 1, 0, p;\n\t}"
        : "=r"(done) : "r"(mb), "r"(phase) : "memory");
    if (!done) {
        asm volatile(
            "{\n\t.reg .pred P1;\n\t"
            "WL_%=:\n\t"
            "mbarrier.try_wait.parity.acquire.cta.shared::cta.b64 P1, [%0], %1, 0x989680;\n\t"
            "@!P1 bra WL_%=;\n\t}"
            :: "r"(mb), "r"(phase) : "memory");
    }
}
__device__ __forceinline__ void bulk_copy_cluster(uint32_t dst, uint32_t src,
                                                  uint32_t bytes, uint32_t mbar) {
    asm volatile(
        "cp.async.bulk.shared::cluster.shared::cta.mbarrier::complete_tx::bytes "
        "[%0], [%1], %2, [%3];"
        :: "r"(dst), "r"(src), "r"(bytes), "r"(mbar) : "memory");
}

__global__ void zero_out(float* out) {
    int i = blockIdx.x * blockDim.x + threadIdx.x;
    if (i < B * T * OUT) out[i] = 0.f;
}

struct __align__(16) SM {
    float r[2][BPC][KTOT];       // 18432 B double-buffered [relu(h); x]
    float red[NSLICE][256];      // 16384 B
    float stage[2][256];         //  2048 B (double-buffered relu staging)
    float wo[HC][OUT];           //  2048 B
    ull   bar[2];
};

__device__ __forceinline__ float effw(int k, int col,
                                      const float* __restrict__ wrec,
                                      const float* __restrict__ wrec_mask,
                                      const float* __restrict__ wi,
                                      const float* __restrict__ si,
                                      const float* __restrict__ wi_mask)
{
    if (k < H) return fabsf(wrec[k * H + col]) * wrec_mask[k * H + col];
    int i = k - H;
    return wi[i * H + col] * si[i] * wi_mask[i * H + col];
}

__global__ void __launch_bounds__(NT, 1) __cluster_dims__(CLUSTER, 1, 1)
rnn_kernel(const float* __restrict__ input,     // [B][T][IN]
           const float* __restrict__ noise,     // [B][T][H]
           const float* __restrict__ wi,
           const float* __restrict__ si,
           const float* __restrict__ wrec,
           const float* __restrict__ bias,
           const float* __restrict__ wo,
           const float* __restrict__ so,
           const float* __restrict__ wi_mask,
           const float* __restrict__ wrec_mask,
           const float* __restrict__ wo_mask,
           const float* __restrict__ h0,
           float* __restrict__ traj,            // [B][T+1][H]
           float* __restrict__ out)             // [B][T][OUT]
{
    __shared__ SM sm;

    const int tid    = threadIdx.x;
    const int rank   = blockIdx.x & (CLUSTER - 1);
    const int batch0 = (blockIdx.x >> 3) * BPC;
    const int col0   = rank * HC;

    // ---- GEMM role: 2 columns x 36-k slice per thread ----
    const int cg = tid & 31;             // column pair 0..31
    const int s  = tid >> 5;             // slice 0..15
    const int c0 = col0 + cg * 2;

    // per-thread effective weights: 2 cols x 36 k -> 36 packed f32x2 regs
    ull wA[18], wB[18];
    #pragma unroll
    for (int i = 0; i < 18; i++) {
        int k0 = s * KS + 2 * i;
        wA[i] = (ull)__float_as_uint(effw(k0,     c0,     wrec, wrec_mask, wi, si, wi_mask))
              | ((ull)__float_as_uint(effw(k0 + 1, c0,     wrec, wrec_mask, wi, si, wi_mask)) << 32);
        wB[i] = (ull)__float_as_uint(effw(k0,     c0 + 1, wrec, wrec_mask, wi, si, wi_mask))
              | ((ull)__float_as_uint(effw(k0 + 1, c0 + 1, wrec, wrec_mask, wi, si, wi_mask)) << 32);
    }

    // ---- shared init ----
    for (int idx = tid; idx < BPC * H; idx += NT) {
        int bb = idx >> 9, k = idx & (H - 1);
        sm.r[0][bb][k] = fmaxf(h0[k], 0.f);
    }
    if (tid < BPC * IN) {
        int bb = tid >> 6, ii = tid & (IN - 1);
        sm.r[0][bb][H + ii] = input[(size_t)(batch0 + bb) * T * IN + ii];
    }
    for (int idx = tid; idx < HC * OUT; idx += NT) {
        int j = idx >> 3, o = idx & (OUT - 1);
        sm.wo[j][o] = wo[(col0 + j) * OUT + o] * so[o] * wo_mask[(col0 + j) * OUT + o];
    }
    const uint32_t bar_sh   = (uint32_t)__cvta_generic_to_shared(&sm.bar[0]);
    const uint32_t r_sh     = (uint32_t)__cvta_generic_to_shared(&sm.r[0][0][0]);
    const uint32_t stage_sh = (uint32_t)__cvta_generic_to_shared(&sm.stage[0][0]);
    if (tid == 0) {
        mbar_init(bar_sh,     1);
        mbar_init(bar_sh + 8, 1);
        mbar_expect(bar_sh,     TXB);    // phase0 of bar0 (copies during t=1)
        mbar_expect(bar_sh + 8, TXB);    // phase0 of bar1 (copies during t=0)
    }

    // ---- update role (threads 0..255 own (bb_u, jg)) ----
    const int bb_u = tid >> 6;
    const int j_u  = tid & 63;
    const int jg   = col0 + j_u;
    float h_reg = 0.f, bias_reg = 0.f;
    const float* np = noise;
    const float* xp = input;
    float* tp = traj;
    float* op = out;
    if (tid < 256) {
        h_reg    = h0[jg];
        bias_reg = bias[jg];
        tp = traj + (size_t)(batch0 + bb_u) * (T + 1) * H + jg;
        *tp = h_reg;                 // t = 0 trajectory row
        tp += H;
        np = noise + (size_t)(batch0 + bb_u) * T * H + jg;
        xp = input + (size_t)(batch0 + bb_u) * T * IN + j_u + IN;  // x_{t+1}
        op = out   + (size_t)(batch0 + bb_u) * T * OUT;
    }

    __syncthreads();
    asm volatile("barrier.cluster.arrive.aligned;" ::: "memory");
    asm volatile("barrier.cluster.wait.aligned;" ::: "memory");

    uint32_t ph[2] = {0u, 0u};

    for (int t = 0; t < T; t++) {
        const int p = t & 1;
        const int q = p ^ 1;

        // prefetch noise(t) / x(t+1): latency hides behind wait + GEMM
        float nval = 0.f, xval = 0.f;
        if (tid < 256) {
            nval = __ldg(np); np += H;
            if (t + 1 < T) { xval = __ldg(xp); xp += IN; }
        }

        if (t > 0) {
            mbar_wait(bar_sh + p * 8, ph[p]);
            ph[p] ^= 1;
            if (tid == 0) mbar_expect(bar_sh + p * 8, TXB);  // re-arm next phase
        }

        // ---- GEMM: 2 cols x 4 batches over this thread's 36-k slice ----
        const float* rb = &sm.r[p][0][s * KS];
        ull aA0 = 0, aA1 = 0, aA2 = 0, aA3 = 0;
        ull aB0 = 0, aB1 = 0, aB2 = 0, aB3 = 0;
        #pragma unroll
        for (int kk = 0; kk < KS / 4; kk++) {
            ulonglong2 v0 = *(const ulonglong2*)(rb + 0 * KTOT + kk * 4);
            ulonglong2 v1 = *(const ulonglong2*)(rb + 1 * KTOT + kk * 4);
            ulonglong2 v2 = *(const ulonglong2*)(rb + 2 * KTOT + kk * 4);
            ulonglong2 v3 = *(const ulonglong2*)(rb + 3 * KTOT + kk * 4);
            ull w0 = wA[2 * kk], w1 = wA[2 * kk + 1];
            ull u0 = wB[2 * kk], u1 = wB[2 * kk + 1];
            fma2(aA0, v0.x, w0); fma2(aA0, v0.y, w1);
            fma2(aB0, v0.x, u0); fma2(aB0, v0.y, u1);
            fma2(aA1, v1.x, w0); fma2(aA1, v1.y, w1);
            fma2(aB1, v1.x, u0); fma2(aB1, v1.y, u1);
            fma2(aA2, v2.x, w0); fma2(aA2, v2.y, w1);
            fma2(aB2, v2.x, u0); fma2(aB2, v2.y, u1);
            fma2(aA3, v3.x, w0); fma2(aA3, v3.y, w1);
            fma2(aB3, v3.x, u0); fma2(aB3, v3.y, u1);
        }
        {
            float2 fa, fb;
            fa = *(float2*)&aA0; fb = *(float2*)&aB0;
            *(float2*)&sm.red[s][0 * 64 + cg * 2] = make_float2(fa.x + fa.y, fb.x + fb.y);
            fa = *(float2*)&aA1; fb = *(float2*)&aB1;
            *(float2*)&sm.red[s][1 * 64 + cg * 2] = make_float2(fa.x + fa.y, fb.x + fb.y);
            fa = *(float2*)&aA2; fb = *(float2*)&aB2;
            *(float2*)&sm.red[s][2 * 64 + cg * 2] = make_float2(fa.x + fa.y, fb.x + fb.y);
            fa = *(float2*)&aA3; fb = *(float2*)&aB3;
            *(float2*)&sm.red[s][3 * 64 + cg * 2] = make_float2(fa.x + fa.y, fb.x + fb.y);
        }
        __syncthreads();

        // ---- reduce 16 slices, state update, stage relu ----
        float hnew = 0.f;
        if (tid < 256) {
            float t0 = sm.red[0][tid]  + sm.red[1][tid];
            float t1 = sm.red[2][tid]  + sm.red[3][tid];
            float t2 = sm.red[4][tid]  + sm.red[5][tid];
            float t3 = sm.red[6][tid]  + sm.red[7][tid];
            float t4 = sm.red[8][tid]  + sm.red[9][tid];
            float t5 = sm.red[10][tid] + sm.red[11][tid];
            float t6 = sm.red[12][tid] + sm.red[13][tid];
            float t7 = sm.red[14][tid] + sm.red[15][tid];
            float tot = ((t0 + t1) + (t2 + t3)) + ((t4 + t5) + (t6 + t7));
            hnew = h_reg + NSTD_C * nval + ALPHA_C * (tot + bias_reg - h_reg);
            h_reg = hnew;
            sm.stage[p][tid] = fmaxf(hnew, 0.f);
            if (t + 1 < T)
                sm.r[q][bb_u][H + j_u] = xval;   // local x_{t+1}
        }
        __syncthreads();

        // ---- 32 bulk copies: stage -> every peer's r[q] chunk, tx-accounted ----
        if (t + 1 < T && tid < 32) {
            int peer = tid & 7, bb = tid >> 3;
            uint32_t src = stage_sh + (uint32_t)(p * 1024 + bb * 256);
            uint32_t ld  = r_sh + (uint32_t)((q * BPC * KTOT + bb * KTOT + col0) * 4);
            uint32_t dst = mapa_sh(ld, peer);
            uint32_t mb  = mapa_sh(bar_sh + q * 8, peer);
            asm volatile("fence.proxy.async.shared::cta;" ::: "memory");
            bulk_copy_cluster(dst, src, 256u, mb);
        }

        // ---- trajectory + fused readout (off the cluster critical path) ----
        if (tid < 256) {
            *tp = hnew; tp += H;
            float v = fmaxf(hnew, 0.f);
            float4 w0 = *(const float4*)&sm.wo[j_u][0];
            float4 w1 = *(const float4*)&sm.wo[j_u][4];
            float p0 = v * w0.x, p1 = v * w0.y, p2 = v * w0.z, p3 = v * w0.w;
            float p4 = v * w1.x, p5 = v * w1.y, p6 = v * w1.z, p7 = v * w1.w;
            #pragma unroll
            for (int off = 16; off; off >>= 1) {
                p0 += __shfl_down_sync(0xffffffffu, p0, off);
                p1 += __shfl_down_sync(0xffffffffu, p1, off);
                p2 += __shfl_down_sync(0xffffffffu, p2, off);
                p3 += __shfl_down_sync(0xffffffffu, p3, off);
                p4 += __shfl_down_sync(0xffffffffu, p4, off);
                p5 += __shfl_down_sync(0xffffffffu, p5, off);
                p6 += __shfl_down_sync(0xffffffffu, p6, off);
                p7 += __shfl_down_sync(0xffffffffu, p7, off);
            }
            if ((tid & 31) == 0) {
                float* ob = op + (size_t)t * OUT;
                atomicAdd(ob + 0, p0); atomicAdd(ob + 1, p1);
                atomicAdd(ob + 2, p2); atomicAdd(ob + 3, p3);
                atomicAdd(ob + 4, p4); atomicAdd(ob + 5, p5);
                atomicAdd(ob + 6, p6); atomicAdd(ob + 7, p7);
            }
        }
    }

    // teardown: no CTA may exit while peers' copies could be in flight
    asm volatile("barrier.cluster.arrive.aligned;" ::: "memory");
    asm volatile("barrier.cluster.wait.aligned;" ::: "memory");
}

// ---------------------------------------------------------------------------
extern "C" void kernel_launch(void* const* d_in, const int* in_sizes, int n_in,
                              void* d_out, int out_size)
{
    (void)in_sizes; (void)n_in; (void)out_size;
    const float* input     = (const float*)d_in[0];
    const float* noise     = (const float*)d_in[1];
    const float* wi        = (const float*)d_in[2];
    const float* si        = (const float*)d_in[3];
    const float* wrec      = (const float*)d_in[4];
    const float* bias      = (const float*)d_in[5];
    const float* wo        = (const float*)d_in[6];
    const float* so        = (const float*)d_in[7];
    const float* wi_mask   = (const float*)d_in[8];
    const float* wrec_mask = (const float*)d_in[9];
    const float* wo_mask   = (const float*)d_in[10];
    const float* h0        = (const float*)d_in[11];

    float* out  = (float*)d_out;
    float* traj = out + (size_t)B * T * OUT;

    zero_out<<<(B * T * OUT + 255) / 256, 256>>>(out);

    rnn_kernel<<<NCLUS * CLUSTER, NT>>>(input, noise, wi, si, wrec, bias, wo, so,
                                        wi_mask, wrec_mask, wo_mask, h0, traj, out);
}